// round 8
// baseline (speedup 1.0000x reference)
#include <cuda_runtime.h>
#include <math.h>

// ---------------- problem constants ----------------
#define BATCH 2
#define NCLS 24
#define NHEADS 8
#define CIN0 1024
#define CPROJ 128

typedef unsigned long long ull;

// ---------------- scratch (static device memory; no allocs) ----------------
__device__ __align__(16) float g_wproj[(size_t)BATCH * NHEADS * CPROJ * CIN0];
__device__ __align__(16) float g_t0[(size_t)BATCH * 1024 * 4 * 6 * 8];
__device__ __align__(16) float g_t1[(size_t)BATCH * 512 * 8 * 12 * 16];
__device__ __align__(16) float g_t2[(size_t)BATCH * 256 * 16 * 24 * 32];
__device__ __align__(16) float g_t3[(size_t)BATCH * 128 * 32 * 48 * 64];
__device__ __align__(16) float g_t4[(size_t)BATCH * 32 * 64 * 96 * 128];
__device__ __align__(16) float g_part[1024 * 16 * 2];
__device__ __align__(16) float g_scale[1024];
__device__ __align__(16) float g_shift[1024];

// ---------------- packed f32x2 helpers (register-only) ----------------
__device__ __forceinline__ void fma2(ull& d, ull a, ull b) {
    asm("fma.rn.f32x2 %0, %1, %2, %0;" : "+l"(d) : "l"(a), "l"(b));
}
__device__ __forceinline__ ull pack2f(float lo, float hi) {
    ull r;
    asm("mov.b64 %0, {%1, %2};" : "=l"(r) : "f"(lo), "f"(hi));
    return r;
}
__device__ __forceinline__ float2 unpk2(ull v) {
    float2 r;
    asm("mov.b64 {%0, %1}, %2;" : "=f"(r.x), "=f"(r.y) : "l"(v));
    return r;
}

// ---------------- hypernet ----------------
__global__ void hyper_kernel(const float* __restrict__ y,
                             const float* __restrict__ tables,
                             float* __restrict__ wout) {
    const int K = CPROJ * CIN0;
    int gid = blockIdx.x * blockDim.x + threadIdx.x;
    if (gid >= NHEADS * K) return;
    int h = gid / K;
    int k = gid - h * K;
    const float* t = tables + (size_t)h * NCLS * K + k;
    float a0 = 0.f, a1 = 0.f;
#pragma unroll
    for (int q = 0; q < NCLS; q++) {
        float tv = t[(size_t)q * K];
        a0 += y[q] * tv;
        a1 += y[NCLS + q] * tv;
    }
    wout[(size_t)0 * NHEADS * K + gid] = a0;
    wout[(size_t)1 * NHEADS * K + gid] = a1;
}

// ---------------- projection (smem-tiled, 8 out-rows per block) ----------------
__global__ void proj_kernel2(const float* __restrict__ x,
                             const float* __restrict__ w,
                             float* __restrict__ out) {
    const int S = 192;
    const int s = threadIdx.x;
    const int hb = blockIdx.x;
    const int b = blockIdx.y;
    const float* xb = x + (size_t)b * 1024 * S + s;
    const float* wb = w + ((size_t)b * 1024 + hb * 8) * 1024;

    __shared__ float wsh[8][192];
    float acc[8];
#pragma unroll
    for (int j = 0; j < 8; j++) acc[j] = 0.f;

    for (int c0 = 0; c0 < 1024; c0 += 192) {
        __syncthreads();
        int cmax = 1024 - c0 < 192 ? 1024 - c0 : 192;
        if (s < cmax) {
#pragma unroll
            for (int j = 0; j < 8; j++) wsh[j][s] = wb[(size_t)j * 1024 + c0 + s];
        }
        __syncthreads();
        for (int cc = 0; cc < cmax; cc++) {
            float xv = xb[(size_t)(c0 + cc) * S];
#pragma unroll
            for (int j = 0; j < 8; j++) acc[j] = fmaf(wsh[j][cc], xv, acc[j]);
        }
    }
#pragma unroll
    for (int j = 0; j < 8; j++)
        out[((size_t)b * 1024 + hb * 8 + j) * S + s] = acc[j];
}

// ---------------- BatchNorm stats (apply is fused into convT staging) ----------
#define BN_NB 16
__global__ void bn_partial(const float* __restrict__ x, int C, int S,
                           float* __restrict__ part) {
    int c = blockIdx.x;
    int nb = blockIdx.y;
    int n = BATCH * S;
    float s1 = 0.f, s2 = 0.f;
    for (int e = nb * blockDim.x + threadIdx.x; e < n; e += BN_NB * blockDim.x) {
        int bb = e / S;
        int sp = e - bb * S;
        float v = x[((size_t)bb * C + c) * S + sp];
        s1 += v;
        s2 += v * v;
    }
    __shared__ float r1[256];
    __shared__ float r2[256];
    r1[threadIdx.x] = s1;
    r2[threadIdx.x] = s2;
    __syncthreads();
    for (int st = 128; st > 0; st >>= 1) {
        if (threadIdx.x < st) {
            r1[threadIdx.x] += r1[threadIdx.x + st];
            r2[threadIdx.x] += r2[threadIdx.x + st];
        }
        __syncthreads();
    }
    if (threadIdx.x == 0) {
        part[(c * BN_NB + nb) * 2 + 0] = r1[0];
        part[(c * BN_NB + nb) * 2 + 1] = r2[0];
    }
}

__global__ void bn_finalize(const float* __restrict__ part, int C, float n,
                            const float* __restrict__ g, const float* __restrict__ be,
                            float* __restrict__ scale, float* __restrict__ shift) {
    int c = blockIdx.x * blockDim.x + threadIdx.x;
    if (c >= C) return;
    float s1 = 0.f, s2 = 0.f;
    for (int i = 0; i < BN_NB; i++) {
        s1 += part[(c * BN_NB + i) * 2 + 0];
        s2 += part[(c * BN_NB + i) * 2 + 1];
    }
    float mean = s1 / n;
    float var = s2 / n - mean * mean;
    var = fmaxf(var, 0.f);
    float sc = g[c] * rsqrtf(var + 1e-5f);
    scale[c] = sc;
    shift[c] = be[c] - mean * sc;
}

// ---------------- ConvTranspose3d k=4 s=2 p=1 : fused BN+ReLU, 8 cells/thread ----
// Per dim taps: out p=0: (d=0,k=1),(d=-1,k=3); p=1: (d=+1,k=0),(d=0,k=2).
// Thread owns 2z x 2y x 2x input cells -> 64 outputs (32 f32x2 accumulators).
// Input staged via LDS.64 (bank-tuned pitch), weights as ulonglong2 LDS.128.
// BN scale/shift + ReLU applied during staging; halo remains exact zero.
template <int TILEY, int TILEX, int PWD, int OG, int CC, bool SIG>
__global__ void __launch_bounds__(2 * (TILEY / 2) * (TILEX / 2) * OG)
convt6_kernel(const float* __restrict__ in, const float* __restrict__ wt,
              const float* __restrict__ bias, const float* __restrict__ scale,
              const float* __restrict__ shift, float* __restrict__ out,
              int Cin, int Cout, int Dz, int Hy, int Wx, int ntx, int nty) {
    constexpr int TXc = TILEX / 2;
    constexpr int TYc = TILEY / 2;
    constexpr int NTS = 2 * TYc * TXc;
    constexpr int NT = NTS * OG;
    constexpr int PH = TILEY + 2;
    constexpr int PS = PH * PWD;       // plane stride (floats)
    constexpr int SDLP = 6 * PS;       // padded staged size
    constexpr int RMAX = (SDLP + NT - 1) / NT;
    constexpr int WN = OG * CC * 16;   // ulonglong2 entries per weight chunk

    __shared__ float vsm[2][SDLP];
    __shared__ ulonglong2 wsm2[2][WN];

    const int tid = threadIdx.x;
    const int og = tid / NTS;
    const int s = tid - og * NTS;
    const int o = blockIdx.y * OG + og;
    const int b = blockIdx.z;
    const int tile = blockIdx.x;
    const int tix = tile % ntx;
    const int t2 = tile / ntx;
    const int tiy = t2 % nty;
    const int tiz = t2 / nty;

    const int txi = s % TXc;
    const int t3 = s / TXc;
    const int tyi = t3 % TYc;
    const int tzi = t3 / TYc;  // 0..1, owns z-cells 2*tzi, 2*tzi+1

    const int bz = tiz * 4, by = tiy * TILEY, bx = tix * TILEX;
    const int S = Dz * Hy * Wx;
    const float* inb = in + (size_t)b * Cin * S;

    // channel-invariant staging offsets; validity packed in a bitmask
    int soff[RMAX];
    unsigned svmask = 0;
#pragma unroll
    for (int r = 0; r < RMAX; r++) {
        int idx = tid + r * NT;
        int i2 = idx < SDLP ? idx : 0;
        int pz_ = i2 / PS;
        int rem = i2 - pz_ * PS;
        int py_ = rem / PWD;
        int px_ = rem - py_ * PWD;
        int gz = bz + pz_ - 1, gy = by + py_ - 1, gx = bx + px_ - 1;
        bool v = (px_ < TILEX + 2) && (gz >= 0 && gz < Dz) &&
                 (gy >= 0 && gy < Hy) && (gx >= 0 && gx < Wx) && (idx < SDLP);
        if (v) svmask |= 1u << r;
        soff[r] = v ? (gz * Hy + gy) * Wx + gx : 0;
    }

    auto stage_w = [&](int chunk) {
        ulonglong2* wd = wsm2[chunk & 1];
        for (int i = tid; i < WN; i += NT) {
            int ogw = i / (CC * 16);
            int r = i - ogw * (CC * 16);
            int cl = r >> 4;
            int kk = r & 15;
            const float* wk = wt +
                (((size_t)(chunk * CC + cl)) * Cout + (blockIdx.y * OG + ogw)) * 64 +
                kk * 4;
            ulonglong2 p;
            p.x = pack2f(wk[1], wk[0]);  // (w1, w0)
            p.y = pack2f(wk[3], wk[2]);  // (w3, w2)
            wd[i] = p;
        }
    };

    ull acc[2][2][2][4];  // [cz][cy][cx][pz*2+py] = (px0, px1)
#pragma unroll
    for (int cz = 0; cz < 2; cz++)
#pragma unroll
        for (int cy = 0; cy < 2; cy++)
#pragma unroll
            for (int cx = 0; cx < 2; cx++)
#pragma unroll
                for (int p = 0; p < 4; p++) acc[cz][cy][cx][p] = 0ull;

    // initial staging (channel 0) with fused BN+ReLU
    stage_w(0);
    {
        const float sc = scale[0], sh = shift[0];
        float* vb = vsm[0];
        const float* pc = inb;
#pragma unroll
        for (int r = 0; r < RMAX; r++) {
            int idx = tid + r * NT;
            if (idx < SDLP) {
                float v = 0.f;
                if ((svmask >> r) & 1u) {
                    v = fmaf(pc[soff[r]], sc, sh);
                    v = v > 0.f ? v : 0.f;
                }
                vb[idx] = v;
            }
        }
    }
    __syncthreads();

    const int tb0 = (2 * tzi * PH + 2 * tyi) * PWD + 2 * txi;
    const int DDt[2][2] = {{0, -1}, {1, 0}};
    const int KKt[2][2] = {{1, 3}, {0, 2}};

    for (int c = 0; c < Cin; c++) {
        if ((c & (CC - 1)) == 0 && c + CC < Cin) stage_w(c / CC + 1);

        // prefetch next channel into registers with fused BN+ReLU
        float pref[RMAX];
        const bool havenext = (c + 1 < Cin);
        if (havenext) {
            const float sc = scale[c + 1], sh = shift[c + 1];
            const float* pc = inb + (size_t)(c + 1) * S;
#pragma unroll
            for (int r = 0; r < RMAX; r++) {
                float v = 0.f;
                if ((svmask >> r) & 1u) {
                    v = fmaf(pc[soff[r]], sc, sh);
                    v = v > 0.f ? v : 0.f;
                }
                pref[r] = v;
            }
        }

        const float* vb = vsm[c & 1];
        const ulonglong2* wc2 =
            wsm2[(c / CC) & 1] + ((size_t)og * CC + (c & (CC - 1))) * 16;

#pragma unroll
        for (int jz = 0; jz < 4; jz++) {
            // plane 2*tzi + jz ; rows 2*tyi + 0..3 ; cols 2*txi + 0..3
            ull vp[4][3];
#pragma unroll
            for (int ry = 0; ry < 4; ry++) {
                const float2* rp = reinterpret_cast<const float2*>(
                    vb + tb0 + jz * PS + ry * PWD);
                const float2 a01 = rp[0];
                const float2 a23 = rp[1];
                vp[ry][0] = pack2f(a01.x, a01.y);
                vp[ry][1] = pack2f(a01.y, a23.x);
                vp[ry][2] = pack2f(a23.x, a23.y);
            }
#pragma unroll
            for (int cz = 0; cz < 2; cz++)
#pragma unroll
                for (int pz = 0; pz < 2; pz++)
#pragma unroll
                    for (int sz = 0; sz < 2; sz++) {
                        if (cz + 1 + DDt[pz][sz] != jz) continue;  // pruned
                        const int kz = KKt[pz][sz];
#pragma unroll
                        for (int py = 0; py < 2; py++)
#pragma unroll
                            for (int sy = 0; sy < 2; sy++) {
                                const int jy0 = 1 + DDt[py][sy];
                                const int ky = KKt[py][sy];
                                const ulonglong2 w2 = wc2[kz * 4 + ky];
#pragma unroll
                                for (int cy = 0; cy < 2; cy++) {
                                    const int row = jy0 + cy;
#pragma unroll
                                    for (int cx = 0; cx < 2; cx++) {
                                        fma2(acc[cz][cy][cx][pz * 2 + py],
                                             vp[row][cx + 1], w2.x);
                                        fma2(acc[cz][cy][cx][pz * 2 + py],
                                             vp[row][cx], w2.y);
                                    }
                                }
                            }
                    }
        }

        if (havenext) {
            float* vb1 = vsm[(c + 1) & 1];
#pragma unroll
            for (int r = 0; r < RMAX; r++) {
                int idx = tid + r * NT;
                if (idx < SDLP) vb1[idx] = pref[r];
            }
        }
        __syncthreads();
    }

    // ---------------- epilogue (exact tiling; scalar stores) ----------------
    const float bv = bias[o];
    const int Ho = 2 * Hy, Wo = 2 * Wx;
    float* ob = out + ((size_t)b * Cout + o) * (size_t)(2 * Dz) * Ho * Wo;

#pragma unroll
    for (int cz = 0; cz < 2; cz++) {
        const int mz = bz + 2 * tzi + cz;
#pragma unroll
        for (int cy = 0; cy < 2; cy++) {
            const int my = by + 2 * tyi + cy;
#pragma unroll
            for (int cx = 0; cx < 2; cx++) {
                const int mx = bx + 2 * txi + cx;
#pragma unroll
                for (int pz = 0; pz < 2; pz++)
#pragma unroll
                    for (int py = 0; py < 2; py++) {
                        float2 a = unpk2(acc[cz][cy][cx][pz * 2 + py]);
                        float r0 = a.x + bv;
                        float r1 = a.y + bv;
                        if (SIG) {
                            r0 = 1.f / (1.f + __expf(-r0));
                            r1 = 1.f / (1.f + __expf(-r1));
                        }
                        size_t base = (size_t)(2 * mz + pz) * Ho * Wo +
                                      (size_t)(2 * my + py) * Wo + (size_t)(2 * mx);
                        ob[base] = r0;
                        ob[base + 1] = r1;
                    }
            }
        }
    }
}

// ---------------- host-side helpers ----------------
static void run_bn_stats(const float* t, int C, int S, const float* g,
                         const float* be, float* part, float* scale, float* shift) {
    dim3 gp(C, BN_NB);
    bn_partial<<<gp, 256>>>(t, C, S, part);
    bn_finalize<<<(C + 127) / 128, 128>>>(part, C, (float)(BATCH * S), g, be, scale, shift);
}

template <int TILEY, int TILEX, int PWD, int OG, int CC, bool SIG>
static void run_convt6(const float* in, const float* wt, const float* bias,
                       const float* scale, const float* shift, float* out,
                       int Cin, int Cout, int Dz, int Hy, int Wx) {
    int ntx = Wx / TILEX;
    int nty = Hy / TILEY;
    int ntz = Dz / 4;
    dim3 grid(ntx * nty * ntz, Cout / OG, BATCH);
    constexpr int NT = 2 * (TILEY / 2) * (TILEX / 2) * OG;
    convt6_kernel<TILEY, TILEX, PWD, OG, CC, SIG>
        <<<grid, NT>>>(in, wt, bias, scale, shift, out, Cin, Cout, Dz, Hy, Wx, ntx, nty);
}

extern "C" void kernel_launch(void* const* d_in, const int* in_sizes, int n_in,
                              void* d_out, int out_size) {
    const float* x_in = (const float*)d_in[0];
    const float* y_in = (const float*)d_in[1];
    const float* tables = (const float*)d_in[2];
    const float* g0 = (const float*)d_in[3];
    const float* be0 = (const float*)d_in[4];
    const float* g1 = (const float*)d_in[5];
    const float* be1 = (const float*)d_in[6];
    const float* g2 = (const float*)d_in[7];
    const float* be2 = (const float*)d_in[8];
    const float* g3 = (const float*)d_in[9];
    const float* be3 = (const float*)d_in[10];
    const float* g4 = (const float*)d_in[11];
    const float* be4 = (const float*)d_in[12];
    const float* w1 = (const float*)d_in[13];
    const float* b1 = (const float*)d_in[14];
    const float* w2 = (const float*)d_in[15];
    const float* b2 = (const float*)d_in[16];
    const float* w3 = (const float*)d_in[17];
    const float* b3 = (const float*)d_in[18];
    const float* w4 = (const float*)d_in[19];
    const float* b4 = (const float*)d_in[20];
    const float* w5 = (const float*)d_in[21];
    const float* b5 = (const float*)d_in[22];

    float *wproj, *t0, *t1, *t2, *t3, *t4, *part, *scale, *shift;
    cudaGetSymbolAddress((void**)&wproj, g_wproj);
    cudaGetSymbolAddress((void**)&t0, g_t0);
    cudaGetSymbolAddress((void**)&t1, g_t1);
    cudaGetSymbolAddress((void**)&t2, g_t2);
    cudaGetSymbolAddress((void**)&t3, g_t3);
    cudaGetSymbolAddress((void**)&t4, g_t4);
    cudaGetSymbolAddress((void**)&part, g_part);
    cudaGetSymbolAddress((void**)&scale, g_scale);
    cudaGetSymbolAddress((void**)&shift, g_shift);

    // 1) hypernet weights
    {
        int tot = NHEADS * CPROJ * CIN0;
        hyper_kernel<<<(tot + 255) / 256, 256>>>(y_in, tables, wproj);
    }
    // 2) dynamic 1x1x1 projection -> t0 [2,1024,4,6,8]
    {
        dim3 pg(128, BATCH);
        proj_kernel2<<<pg, 192>>>(x_in, wproj, t0);
    }
    // 3) decoder stack — BN apply fused into each convT's staging
    run_bn_stats(t0, 1024, 4 * 6 * 8, g0, be0, part, scale, shift);
    run_convt6<6, 8, 14, 4, 16, false>(t0, w1, b1, scale, shift, t1,
                                       1024, 512, 4, 6, 8);
    run_bn_stats(t1, 512, 8 * 12 * 16, g1, be1, part, scale, shift);
    run_convt6<12, 16, 20, 1, 32, false>(t1, w2, b2, scale, shift, t2,
                                         512, 256, 8, 12, 16);
    run_bn_stats(t2, 256, 16 * 24 * 32, g2, be2, part, scale, shift);
    run_convt6<12, 16, 20, 1, 32, false>(t2, w3, b3, scale, shift, t3,
                                         256, 128, 16, 24, 32);
    run_bn_stats(t3, 128, 32 * 48 * 64, g3, be3, part, scale, shift);
    run_convt6<12, 16, 20, 1, 32, false>(t3, w4, b4, scale, shift, t4,
                                         128, 32, 32, 48, 64);
    run_bn_stats(t4, 32, 64 * 96 * 128, g4, be4, part, scale, shift);
    run_convt6<12, 16, 20, 1, 32, true>(t4, w5, b5, scale, shift, (float*)d_out,
                                        32, 1, 64, 96, 128);
}

// round 9
// speedup vs baseline: 1.6560x; 1.6560x over previous
#include <cuda_runtime.h>
#include <math.h>

// ---------------- problem constants ----------------
#define BATCH 2
#define NCLS 24
#define NHEADS 8
#define CIN0 1024
#define CPROJ 128

typedef unsigned long long ull;

// ---------------- scratch (static device memory; no allocs) ----------------
__device__ __align__(16) float g_wproj[(size_t)BATCH * NHEADS * CPROJ * CIN0];
__device__ __align__(16) float g_t0[(size_t)BATCH * 1024 * 4 * 6 * 8];
__device__ __align__(16) float g_t1[(size_t)BATCH * 512 * 8 * 12 * 16];
__device__ __align__(16) float g_t2[(size_t)BATCH * 256 * 16 * 24 * 32];
__device__ __align__(16) float g_t3[(size_t)BATCH * 128 * 32 * 48 * 64];
__device__ __align__(16) float g_t4[(size_t)BATCH * 32 * 64 * 96 * 128];
__device__ __align__(16) float g_part[1024 * 16 * 2];
__device__ __align__(16) float g_scale[1024];
__device__ __align__(16) float g_shift[1024];

// ---------------- packed f32x2 helpers (register-only) ----------------
__device__ __forceinline__ void fma2(ull& d, ull a, ull b) {
    asm("fma.rn.f32x2 %0, %1, %2, %0;" : "+l"(d) : "l"(a), "l"(b));
}
__device__ __forceinline__ ull pack2f(float lo, float hi) {
    ull r;
    asm("mov.b64 %0, {%1, %2};" : "=l"(r) : "f"(lo), "f"(hi));
    return r;
}
__device__ __forceinline__ float2 unpk2(ull v) {
    float2 r;
    asm("mov.b64 {%0, %1}, %2;" : "=f"(r.x), "=f"(r.y) : "l"(v));
    return r;
}

// ---------------- hypernet ----------------
__global__ void hyper_kernel(const float* __restrict__ y,
                             const float* __restrict__ tables,
                             float* __restrict__ wout) {
    const int K = CPROJ * CIN0;
    int gid = blockIdx.x * blockDim.x + threadIdx.x;
    if (gid >= NHEADS * K) return;
    int h = gid / K;
    int k = gid - h * K;
    const float* t = tables + (size_t)h * NCLS * K + k;
    float a0 = 0.f, a1 = 0.f;
#pragma unroll
    for (int q = 0; q < NCLS; q++) {
        float tv = t[(size_t)q * K];
        a0 += y[q] * tv;
        a1 += y[NCLS + q] * tv;
    }
    wout[(size_t)0 * NHEADS * K + gid] = a0;
    wout[(size_t)1 * NHEADS * K + gid] = a1;
}

// ---------------- projection (smem-tiled, 8 out-rows per block) ----------------
__global__ void proj_kernel2(const float* __restrict__ x,
                             const float* __restrict__ w,
                             float* __restrict__ out) {
    const int S = 192;
    const int s = threadIdx.x;
    const int hb = blockIdx.x;
    const int b = blockIdx.y;
    const float* xb = x + (size_t)b * 1024 * S + s;
    const float* wb = w + ((size_t)b * 1024 + hb * 8) * 1024;

    __shared__ float wsh[8][192];
    float acc[8];
#pragma unroll
    for (int j = 0; j < 8; j++) acc[j] = 0.f;

    for (int c0 = 0; c0 < 1024; c0 += 192) {
        __syncthreads();
        int cmax = 1024 - c0 < 192 ? 1024 - c0 : 192;
        if (s < cmax) {
#pragma unroll
            for (int j = 0; j < 8; j++) wsh[j][s] = wb[(size_t)j * 1024 + c0 + s];
        }
        __syncthreads();
        for (int cc = 0; cc < cmax; cc++) {
            float xv = xb[(size_t)(c0 + cc) * S];
#pragma unroll
            for (int j = 0; j < 8; j++) acc[j] = fmaf(wsh[j][cc], xv, acc[j]);
        }
    }
#pragma unroll
    for (int j = 0; j < 8; j++)
        out[((size_t)b * 1024 + hb * 8 + j) * S + s] = acc[j];
}

// ---------------- BatchNorm ----------------
#define BN_NB 16
__global__ void bn_partial(const float* __restrict__ x, int C, int S,
                           float* __restrict__ part) {
    int c = blockIdx.x;
    int nb = blockIdx.y;
    int n = BATCH * S;
    float s1 = 0.f, s2 = 0.f;
    for (int e = nb * blockDim.x + threadIdx.x; e < n; e += BN_NB * blockDim.x) {
        int bb = e / S;
        int sp = e - bb * S;
        float v = x[((size_t)bb * C + c) * S + sp];
        s1 += v;
        s2 += v * v;
    }
    __shared__ float r1[256];
    __shared__ float r2[256];
    r1[threadIdx.x] = s1;
    r2[threadIdx.x] = s2;
    __syncthreads();
    for (int st = 128; st > 0; st >>= 1) {
        if (threadIdx.x < st) {
            r1[threadIdx.x] += r1[threadIdx.x + st];
            r2[threadIdx.x] += r2[threadIdx.x + st];
        }
        __syncthreads();
    }
    if (threadIdx.x == 0) {
        part[(c * BN_NB + nb) * 2 + 0] = r1[0];
        part[(c * BN_NB + nb) * 2 + 1] = r2[0];
    }
}

__global__ void bn_finalize(const float* __restrict__ part, int C, float n,
                            const float* __restrict__ g, const float* __restrict__ be,
                            float* __restrict__ scale, float* __restrict__ shift) {
    int c = blockIdx.x * blockDim.x + threadIdx.x;
    if (c >= C) return;
    float s1 = 0.f, s2 = 0.f;
    for (int i = 0; i < BN_NB; i++) {
        s1 += part[(c * BN_NB + i) * 2 + 0];
        s2 += part[(c * BN_NB + i) * 2 + 1];
    }
    float mean = s1 / n;
    float var = s2 / n - mean * mean;
    var = fmaxf(var, 0.f);
    float sc = g[c] * rsqrtf(var + 1e-5f);
    scale[c] = sc;
    shift[c] = be[c] - mean * sc;
}

__global__ void bn_apply_relu(float* __restrict__ x, int C, int S,
                              const float* __restrict__ scale,
                              const float* __restrict__ shift) {
    size_t gid = (size_t)blockIdx.x * blockDim.x + threadIdx.x;
    size_t total = (size_t)BATCH * C * S;
    if (gid >= total) return;
    int c = (int)((gid / S) % C);
    float v = fmaf(x[gid], scale[c], shift[c]);
    x[gid] = v > 0.f ? v : 0.f;
}

// ---------------- ConvTranspose3d k=4 s=2 p=1 : f32x2, de-interleaved smem ----
// Per dim: out px=0 taps (d=0,k=1),(d=-1,k=3) ; px=1 taps (d=+1,k=0),(d=0,k=2).
// Cell m: px0 += v[m]*w1 + v[m-1]*w3 ; px1 += v[m+1]*w0 + v[m]*w2.
// Staged tile layout: per padded plane (PS words) x padded row (RW words):
//   even x-positions at cols [0..TXc], odd x-positions at cols [OB..OB+TXc].
// Thread reads e[txi], e[txi+1], o[txi], o[txi+1] -> stride-1, bank-conflict-free
// with warp shape {txi}x{tyi 0..3} and RW/PS strides tuned mod 32.
template <int TILEY, int TILEX, int RW, int OB, int PSPAD, int OG, int CC, bool SIG>
__global__ void __launch_bounds__(TILEY * TILEX * OG)
convt7_kernel(const float* __restrict__ in, const float* __restrict__ wt,
              const float* __restrict__ bias, float* __restrict__ out,
              int Cin, int Cout, int Dz, int Hy, int Wx, int ntx, int nty) {
    constexpr int TXc = TILEX / 2;
    constexpr int TYc = TILEY / 2;
    constexpr int NTS = TILEY * TILEX;
    constexpr int NT = NTS * OG;
    constexpr int PH = TILEY + 2;
    constexpr int PS = PH * RW + PSPAD;  // plane stride (words)
    constexpr int SDLP = 6 * PS;
    constexpr int RMAX = (SDLP + NT - 1) / NT;
    constexpr int WPC = OG * CC * 32;  // packed ull weight entries per chunk

    __shared__ float vsm[2][SDLP];
    __shared__ ull wsmU[2][WPC];

    const int tid = threadIdx.x;
    const int og = tid / NTS;
    const int s = tid - og * NTS;
    const int o = blockIdx.y * OG + og;
    const int b = blockIdx.z;
    const int tile = blockIdx.x;
    const int tix = tile % ntx;
    const int t2 = tile / ntx;
    const int tiy = t2 % nty;
    const int tiz = t2 / nty;

    const int txi = s % TXc;
    const int t3 = s / TXc;
    const int tyi = t3 % TYc;
    const int tzi = t3 / TYc;  // 0..3

    const int bz = tiz * 4, by = tiy * TILEY, bx = tix * TILEX;
    const int S = Dz * Hy * Wx;
    const float* inb = in + (size_t)b * Cin * S;

    // channel-invariant staging offsets into the de-interleaved layout
    int soff[RMAX];
    unsigned sw_act = 0;   // this r writes smem
    unsigned sw_vld = 0;   // and reads gmem (else zero halo)
#pragma unroll
    for (int r = 0; r < RMAX; r++) {
        int idx = tid + r * NT;
        int i2 = idx < SDLP ? idx : 0;
        int plane = i2 / PS;
        int rem = i2 - plane * PS;
        int row = rem / RW;
        int col = rem - row * RW;
        bool inrow = (row < PH) && (idx < SDLP);
        bool iseven = col <= TXc;
        bool isodd = (col >= OB) && (col <= OB + TXc);
        bool act = inrow && (iseven || isodd);
        int px = iseven ? 2 * col : 2 * (col - OB) + 1;
        int gz = bz + plane - 1, gy = by + row - 1, gx = bx + px - 1;
        bool vld = act && (gz >= 0 && gz < Dz) && (gy >= 0 && gy < Hy) &&
                   (gx >= 0 && gx < Wx);
        if (act) sw_act |= 1u << r;
        if (vld) sw_vld |= 1u << r;
        soff[r] = vld ? (gz * Hy + gy) * Wx + gx : 0;
    }

    auto stage_w = [&](int chunk) {
        ull* wd = wsmU[chunk & 1];
        for (int i = tid; i < WPC; i += NT) {
            int ogw = i / (CC * 32);
            int r = i - ogw * (CC * 32);
            int cl = r >> 5;
            int e = r & 31;
            int kzky = e >> 1;
            int half = e & 1;
            const float* wk = wt +
                (((size_t)(chunk * CC + cl)) * Cout + (blockIdx.y * OG + ogw)) * 64 +
                kzky * 4;
            float lo, hi;
            if (half == 0) { lo = wk[1]; hi = wk[0]; }
            else           { lo = wk[3]; hi = wk[2]; }
            wd[i] = pack2f(lo, hi);
        }
    };

    ull acc[2][2][4];  // [cy][cx][pz*2+py] = (px0, px1)
#pragma unroll
    for (int cy = 0; cy < 2; cy++)
#pragma unroll
        for (int cx = 0; cx < 2; cx++)
#pragma unroll
            for (int p = 0; p < 4; p++) acc[cy][cx][p] = 0ull;

    // initial staging (channel 0)
    stage_w(0);
    {
        float* vb = vsm[0];
        const float* pc = inb;
#pragma unroll
        for (int r = 0; r < RMAX; r++) {
            if ((sw_act >> r) & 1u)
                vb[tid + r * NT] = ((sw_vld >> r) & 1u) ? pc[soff[r]] : 0.f;
        }
    }
    __syncthreads();

    const int DDt[2][2] = {{0, -1}, {1, 0}};
    const int KKt[2][2] = {{1, 3}, {0, 2}};
    const int rbase = 2 * tyi * RW + txi;

    for (int c = 0; c < Cin; c++) {
        if ((c & (CC - 1)) == 0 && c + CC < Cin) stage_w(c / CC + 1);

        // prefetch next channel into registers
        float pref[RMAX];
        const bool havenext = (c + 1 < Cin);
        if (havenext) {
            const float* pc = inb + (size_t)(c + 1) * S;
#pragma unroll
            for (int r = 0; r < RMAX; r++) {
                pref[r] = ((sw_vld >> r) & 1u) ? pc[soff[r]] : 0.f;
            }
        }

        const float* vb = vsm[c & 1];
        const ull* wcU = wsmU[(c / CC) & 1] + ((size_t)og * CC + (c & (CC - 1))) * 32;

#pragma unroll
        for (int jz = 0; jz < 3; jz++) {
            ull vp[4][3];
#pragma unroll
            for (int ry = 0; ry < 4; ry++) {
                const float* rp = vb + (tzi + jz) * PS + rbase + ry * RW;
                float e0 = rp[0];
                float e1 = rp[1];
                float o0 = rp[OB];
                float o1 = rp[OB + 1];
                vp[ry][0] = pack2f(e0, o0);  // (x0, x1)
                vp[ry][1] = pack2f(o0, e1);  // (x1, x2)
                vp[ry][2] = pack2f(e1, o1);  // (x2, x3)
            }
#pragma unroll
            for (int pz = 0; pz < 2; pz++)
#pragma unroll
                for (int sz = 0; sz < 2; sz++) {
                    if (1 + DDt[pz][sz] != jz) continue;  // compile-time pruned
                    const int kz = KKt[pz][sz];
#pragma unroll
                    for (int py = 0; py < 2; py++)
#pragma unroll
                        for (int sy = 0; sy < 2; sy++) {
                            const int jy0 = 1 + DDt[py][sy];
                            const int ky = KKt[py][sy];
                            const ull wa = wcU[(kz * 4 + ky) * 2 + 0];  // (w1,w0)
                            const ull wb = wcU[(kz * 4 + ky) * 2 + 1];  // (w3,w2)
#pragma unroll
                            for (int cy = 0; cy < 2; cy++) {
                                const int row = jy0 + cy;
#pragma unroll
                                for (int cx = 0; cx < 2; cx++) {
                                    fma2(acc[cy][cx][pz * 2 + py], vp[row][cx + 1], wa);
                                    fma2(acc[cy][cx][pz * 2 + py], vp[row][cx], wb);
                                }
                            }
                        }
                }
        }

        if (havenext) {
            float* vb1 = vsm[(c + 1) & 1];
#pragma unroll
            for (int r = 0; r < RMAX; r++) {
                if ((sw_act >> r) & 1u) vb1[tid + r * NT] = pref[r];
            }
        }
        __syncthreads();
    }

    // ---------------- epilogue (scalar stores; exact tiling) ----------------
    const int mz = bz + tzi;
    if (mz >= Dz) return;
    const float bv = bias[o];
    const int Ho = 2 * Hy, Wo = 2 * Wx;
    float* ob = out + ((size_t)b * Cout + o) * (size_t)(2 * Dz) * Ho * Wo;
    const int my0 = by + 2 * tyi;
    const int mx0 = bx + 2 * txi;

#pragma unroll
    for (int cy = 0; cy < 2; cy++) {
        int my = my0 + cy;
        if (my >= Hy) continue;
#pragma unroll
        for (int cx = 0; cx < 2; cx++) {
            int mx = mx0 + cx;
            if (mx >= Wx) continue;
#pragma unroll
            for (int pz = 0; pz < 2; pz++)
#pragma unroll
                for (int py = 0; py < 2; py++) {
                    float2 a = unpk2(acc[cy][cx][pz * 2 + py]);
                    float r0 = a.x + bv;
                    float r1 = a.y + bv;
                    if (SIG) {
                        r0 = 1.f / (1.f + __expf(-r0));
                        r1 = 1.f / (1.f + __expf(-r1));
                    }
                    size_t base = (size_t)(2 * mz + pz) * Ho * Wo +
                                  (size_t)(2 * my + py) * Wo + (size_t)(2 * mx);
                    ob[base] = r0;
                    ob[base + 1] = r1;
                }
        }
    }
}

// ---------------- host-side helpers ----------------
static void run_bn(float* t, int C, int S, const float* g, const float* be,
                   float* part, float* scale, float* shift) {
    dim3 gp(C, BN_NB);
    bn_partial<<<gp, 256>>>(t, C, S, part);
    bn_finalize<<<(C + 127) / 128, 128>>>(part, C, (float)(BATCH * S), g, be, scale, shift);
    size_t total = (size_t)BATCH * C * S;
    bn_apply_relu<<<(unsigned)((total + 255) / 256), 256>>>(t, C, S, scale, shift);
}

template <int TILEY, int TILEX, int RW, int OB, int PSPAD, int OG, int CC, bool SIG>
static void run_convt7(const float* in, const float* wt, const float* bias,
                       float* out, int Cin, int Cout, int Dz, int Hy, int Wx) {
    int ntx = Wx / TILEX;
    int nty = Hy / TILEY;
    int ntz = Dz / 4;
    dim3 grid(ntx * nty * ntz, Cout / OG, BATCH);
    convt7_kernel<TILEY, TILEX, RW, OB, PSPAD, OG, CC, SIG>
        <<<grid, TILEY * TILEX * OG>>>(in, wt, bias, out, Cin, Cout, Dz, Hy, Wx,
                                       ntx, nty);
}

extern "C" void kernel_launch(void* const* d_in, const int* in_sizes, int n_in,
                              void* d_out, int out_size) {
    const float* x_in = (const float*)d_in[0];
    const float* y_in = (const float*)d_in[1];
    const float* tables = (const float*)d_in[2];
    const float* g0 = (const float*)d_in[3];
    const float* be0 = (const float*)d_in[4];
    const float* g1 = (const float*)d_in[5];
    const float* be1 = (const float*)d_in[6];
    const float* g2 = (const float*)d_in[7];
    const float* be2 = (const float*)d_in[8];
    const float* g3 = (const float*)d_in[9];
    const float* be3 = (const float*)d_in[10];
    const float* g4 = (const float*)d_in[11];
    const float* be4 = (const float*)d_in[12];
    const float* w1 = (const float*)d_in[13];
    const float* b1 = (const float*)d_in[14];
    const float* w2 = (const float*)d_in[15];
    const float* b2 = (const float*)d_in[16];
    const float* w3 = (const float*)d_in[17];
    const float* b3 = (const float*)d_in[18];
    const float* w4 = (const float*)d_in[19];
    const float* b4 = (const float*)d_in[20];
    const float* w5 = (const float*)d_in[21];
    const float* b5 = (const float*)d_in[22];

    float *wproj, *t0, *t1, *t2, *t3, *t4, *part, *scale, *shift;
    cudaGetSymbolAddress((void**)&wproj, g_wproj);
    cudaGetSymbolAddress((void**)&t0, g_t0);
    cudaGetSymbolAddress((void**)&t1, g_t1);
    cudaGetSymbolAddress((void**)&t2, g_t2);
    cudaGetSymbolAddress((void**)&t3, g_t3);
    cudaGetSymbolAddress((void**)&t4, g_t4);
    cudaGetSymbolAddress((void**)&part, g_part);
    cudaGetSymbolAddress((void**)&scale, g_scale);
    cudaGetSymbolAddress((void**)&shift, g_shift);

    // 1) hypernet weights
    {
        int tot = NHEADS * CPROJ * CIN0;
        hyper_kernel<<<(tot + 255) / 256, 256>>>(y_in, tables, wproj);
    }
    // 2) dynamic 1x1x1 projection -> t0 [2,1024,4,6,8]
    {
        dim3 pg(128, BATCH);
        proj_kernel2<<<pg, 192>>>(x_in, wproj, t0);
    }
    // 3) decoder stack
    // L1: 1024->512 @ 4x6x8   : TILEY=6,TILEX=8, RW=18,OB=8, PS=8*18+28=172, OG=4,CC=16
    // L2: 512->256  @ 8x12x16 : TILEY=4,TILEX=16,RW=24,OB=12,PS=6*24+24=168, OG=2,CC=32
    // L3+: TILEY=8,TILEX=16, RW=20,OB=10, PS=10*20, OG=1, CC=32 (warp-clean, CF)
    run_bn(t0, 1024, 4 * 6 * 8, g0, be0, part, scale, shift);
    run_convt7<6, 8, 18, 8, 28, 4, 16, false>(t0, w1, b1, t1, 1024, 512, 4, 6, 8);
    run_bn(t1, 512, 8 * 12 * 16, g1, be1, part, scale, shift);
    run_convt7<4, 16, 24, 12, 24, 2, 32, false>(t1, w2, b2, t2, 512, 256, 8, 12, 16);
    run_bn(t2, 256, 16 * 24 * 32, g2, be2, part, scale, shift);
    run_convt7<8, 16, 20, 10, 0, 1, 32, false>(t2, w3, b3, t3, 256, 128, 16, 24, 32);
    run_bn(t3, 128, 32 * 48 * 64, g3, be3, part, scale, shift);
    run_convt7<8, 16, 20, 10, 0, 1, 32, false>(t3, w4, b4, t4, 128, 32, 32, 48, 64);
    run_bn(t4, 32, 64 * 96 * 128, g4, be4, part, scale, shift);
    run_convt7<8, 16, 20, 10, 0, 1, 32, true>(t4, w5, b5, (float*)d_out, 32, 1,
                                              64, 96, 128);
}

// round 10
// speedup vs baseline: 1.7635x; 1.0649x over previous
#include <cuda_runtime.h>
#include <math.h>

// ---------------- problem constants ----------------
#define BATCH 2
#define NCLS 24
#define NHEADS 8
#define CIN0 1024
#define CPROJ 128

typedef unsigned long long ull;

// ---------------- scratch (static device memory; no allocs) ----------------
__device__ __align__(16) float g_wproj[(size_t)BATCH * NHEADS * CPROJ * CIN0];
__device__ __align__(16) float g_t0[(size_t)BATCH * 1024 * 4 * 6 * 8];
__device__ __align__(16) float g_t1[(size_t)BATCH * 512 * 8 * 12 * 16];
__device__ __align__(16) float g_t2[(size_t)BATCH * 256 * 16 * 24 * 32];
__device__ __align__(16) float g_t3[(size_t)BATCH * 128 * 32 * 48 * 64];
__device__ __align__(16) float g_t4[(size_t)BATCH * 32 * 64 * 96 * 128];
__device__ __align__(16) float g_part[1024 * 16 * 2];
__device__ __align__(16) float g_scale[1024];
__device__ __align__(16) float g_shift[1024];

// ---------------- packed f32x2 helpers (register-only) ----------------
__device__ __forceinline__ void fma2(ull& d, ull a, ull b) {
    asm("fma.rn.f32x2 %0, %1, %2, %0;" : "+l"(d) : "l"(a), "l"(b));
}
__device__ __forceinline__ ull pack2f(float lo, float hi) {
    ull r;
    asm("mov.b64 %0, {%1, %2};" : "=l"(r) : "f"(lo), "f"(hi));
    return r;
}
__device__ __forceinline__ float2 unpk2(ull v) {
    float2 r;
    asm("mov.b64 {%0, %1}, %2;" : "=f"(r.x), "=f"(r.y) : "l"(v));
    return r;
}

// ---------------- hypernet ----------------
__global__ void hyper_kernel(const float* __restrict__ y,
                             const float* __restrict__ tables,
                             float* __restrict__ wout) {
    const int K = CPROJ * CIN0;
    int gid = blockIdx.x * blockDim.x + threadIdx.x;
    if (gid >= NHEADS * K) return;
    int h = gid / K;
    int k = gid - h * K;
    const float* t = tables + (size_t)h * NCLS * K + k;
    float a0 = 0.f, a1 = 0.f;
#pragma unroll
    for (int q = 0; q < NCLS; q++) {
        float tv = t[(size_t)q * K];
        a0 += y[q] * tv;
        a1 += y[NCLS + q] * tv;
    }
    wout[(size_t)0 * NHEADS * K + gid] = a0;
    wout[(size_t)1 * NHEADS * K + gid] = a1;
}

// ---------------- projection (smem-tiled, 8 out-rows per block) ----------------
__global__ void proj_kernel2(const float* __restrict__ x,
                             const float* __restrict__ w,
                             float* __restrict__ out) {
    const int S = 192;
    const int s = threadIdx.x;
    const int hb = blockIdx.x;
    const int b = blockIdx.y;
    const float* xb = x + (size_t)b * 1024 * S + s;
    const float* wb = w + ((size_t)b * 1024 + hb * 8) * 1024;

    __shared__ float wsh[8][192];
    float acc[8];
#pragma unroll
    for (int j = 0; j < 8; j++) acc[j] = 0.f;

    for (int c0 = 0; c0 < 1024; c0 += 192) {
        __syncthreads();
        int cmax = 1024 - c0 < 192 ? 1024 - c0 : 192;
        if (s < cmax) {
#pragma unroll
            for (int j = 0; j < 8; j++) wsh[j][s] = wb[(size_t)j * 1024 + c0 + s];
        }
        __syncthreads();
        for (int cc = 0; cc < cmax; cc++) {
            float xv = xb[(size_t)(c0 + cc) * S];
#pragma unroll
            for (int j = 0; j < 8; j++) acc[j] = fmaf(wsh[j][cc], xv, acc[j]);
        }
    }
#pragma unroll
    for (int j = 0; j < 8; j++)
        out[((size_t)b * 1024 + hb * 8 + j) * S + s] = acc[j];
}

// ---------------- BatchNorm ----------------
#define BN_NB 16
__global__ void bn_partial(const float* __restrict__ x, int C, int S,
                           float* __restrict__ part) {
    int c = blockIdx.x;
    int nb = blockIdx.y;
    int n = BATCH * S;
    float s1 = 0.f, s2 = 0.f;
    for (int e = nb * blockDim.x + threadIdx.x; e < n; e += BN_NB * blockDim.x) {
        int bb = e / S;
        int sp = e - bb * S;
        float v = x[((size_t)bb * C + c) * S + sp];
        s1 += v;
        s2 += v * v;
    }
    __shared__ float r1[256];
    __shared__ float r2[256];
    r1[threadIdx.x] = s1;
    r2[threadIdx.x] = s2;
    __syncthreads();
    for (int st = 128; st > 0; st >>= 1) {
        if (threadIdx.x < st) {
            r1[threadIdx.x] += r1[threadIdx.x + st];
            r2[threadIdx.x] += r2[threadIdx.x + st];
        }
        __syncthreads();
    }
    if (threadIdx.x == 0) {
        part[(c * BN_NB + nb) * 2 + 0] = r1[0];
        part[(c * BN_NB + nb) * 2 + 1] = r2[0];
    }
}

__global__ void bn_finalize(const float* __restrict__ part, int C, float n,
                            const float* __restrict__ g, const float* __restrict__ be,
                            float* __restrict__ scale, float* __restrict__ shift) {
    int c = blockIdx.x * blockDim.x + threadIdx.x;
    if (c >= C) return;
    float s1 = 0.f, s2 = 0.f;
    for (int i = 0; i < BN_NB; i++) {
        s1 += part[(c * BN_NB + i) * 2 + 0];
        s2 += part[(c * BN_NB + i) * 2 + 1];
    }
    float mean = s1 / n;
    float var = s2 / n - mean * mean;
    var = fmaxf(var, 0.f);
    float sc = g[c] * rsqrtf(var + 1e-5f);
    scale[c] = sc;
    shift[c] = be[c] - mean * sc;
}

__global__ void bn_apply_relu(float* __restrict__ x, int C, int S,
                              const float* __restrict__ scale,
                              const float* __restrict__ shift) {
    size_t gid = (size_t)blockIdx.x * blockDim.x + threadIdx.x;
    size_t total = (size_t)BATCH * C * S;
    if (gid >= total) return;
    int c = (int)((gid / S) % C);
    float v = fmaf(x[gid], scale[c], shift[c]);
    x[gid] = v > 0.f ? v : 0.f;
}

// ---------------- ConvTranspose3d k=4 s=2 p=1 : f32x2 + OC output chans/thread --
// Per dim: out px=0 taps (d=0,k=1),(d=-1,k=3) ; px=1 taps (d=+1,k=0),(d=0,k=2).
// Cell m: px0 += v[m]*w1 + v[m-1]*w3 ; px1 += v[m+1]*w0 + v[m]*w2.
// De-interleaved staged layout (even x at cols [0..TXc], odd at [OB..OB+TXc]).
// Each thread computes OC consecutive output channels from ONE set of v loads,
// amortizing all LDS/pack/staging/barrier cost 2x. R9 skeleton otherwise.
template <int TILEY, int TILEX, int RW, int OB, int PSPAD, int OG, int OC, int CC,
          bool SIG>
__global__ void __launch_bounds__(TILEY * TILEX * OG)
convt8_kernel(const float* __restrict__ in, const float* __restrict__ wt,
              const float* __restrict__ bias, float* __restrict__ out,
              int Cin, int Cout, int Dz, int Hy, int Wx, int ntx, int nty) {
    constexpr int TXc = TILEX / 2;
    constexpr int TYc = TILEY / 2;
    constexpr int NTS = TILEY * TILEX;
    constexpr int NT = NTS * OG;
    constexpr int PH = TILEY + 2;
    constexpr int PS = PH * RW + PSPAD;  // plane stride (words)
    constexpr int SDLP = 6 * PS;
    constexpr int RMAX = (SDLP + NT - 1) / NT;
    constexpr int WPC = OG * OC * CC * 32;  // packed ull weight entries per chunk

    __shared__ float vsm[2][SDLP];
    __shared__ ull wsmU[2][WPC];

    const int tid = threadIdx.x;
    const int og = tid / NTS;
    const int s = tid - og * NTS;
    const int obase = blockIdx.y * OG * OC + og * OC;  // first of OC outputs
    const int b = blockIdx.z;
    const int tile = blockIdx.x;
    const int tix = tile % ntx;
    const int t2 = tile / ntx;
    const int tiy = t2 % nty;
    const int tiz = t2 / nty;

    const int txi = s % TXc;
    const int t3 = s / TXc;
    const int tyi = t3 % TYc;
    const int tzi = t3 / TYc;  // 0..3

    const int bz = tiz * 4, by = tiy * TILEY, bx = tix * TILEX;
    const int S = Dz * Hy * Wx;
    const float* inb = in + (size_t)b * Cin * S;

    // channel-invariant staging offsets into the de-interleaved layout
    int soff[RMAX];
    unsigned sw_act = 0;
    unsigned sw_vld = 0;
#pragma unroll
    for (int r = 0; r < RMAX; r++) {
        int idx = tid + r * NT;
        int i2 = idx < SDLP ? idx : 0;
        int plane = i2 / PS;
        int rem = i2 - plane * PS;
        int row = rem / RW;
        int col = rem - row * RW;
        bool inrow = (row < PH) && (idx < SDLP);
        bool iseven = col <= TXc;
        bool isodd = (col >= OB) && (col <= OB + TXc);
        bool act = inrow && (iseven || isodd);
        int px = iseven ? 2 * col : 2 * (col - OB) + 1;
        int gz = bz + plane - 1, gy = by + row - 1, gx = bx + px - 1;
        bool vld = act && (gz >= 0 && gz < Dz) && (gy >= 0 && gy < Hy) &&
                   (gx >= 0 && gx < Wx);
        if (act) sw_act |= 1u << r;
        if (vld) sw_vld |= 1u << r;
        soff[r] = vld ? (gz * Hy + gy) * Wx + gx : 0;
    }

    auto stage_w = [&](int chunk) {
        ull* wd = wsmU[chunk & 1];
        for (int i = tid; i < WPC; i += NT) {
            int ogc = i / (CC * 32);  // 0 .. OG*OC-1
            int r = i - ogc * (CC * 32);
            int cl = r >> 5;
            int e = r & 31;
            int kzky = e >> 1;
            int half = e & 1;
            const float* wk = wt +
                (((size_t)(chunk * CC + cl)) * Cout +
                 (blockIdx.y * OG * OC + ogc)) * 64 +
                kzky * 4;
            float lo, hi;
            if (half == 0) { lo = wk[1]; hi = wk[0]; }
            else           { lo = wk[3]; hi = wk[2]; }
            wd[i] = pack2f(lo, hi);
        }
    };

    ull acc[OC][2][2][4];  // [oc][cy][cx][pz*2+py] = (px0, px1)
#pragma unroll
    for (int oc = 0; oc < OC; oc++)
#pragma unroll
        for (int cy = 0; cy < 2; cy++)
#pragma unroll
            for (int cx = 0; cx < 2; cx++)
#pragma unroll
                for (int p = 0; p < 4; p++) acc[oc][cy][cx][p] = 0ull;

    // initial staging (channel 0)
    stage_w(0);
    {
        float* vb = vsm[0];
        const float* pc = inb;
#pragma unroll
        for (int r = 0; r < RMAX; r++) {
            if ((sw_act >> r) & 1u)
                vb[tid + r * NT] = ((sw_vld >> r) & 1u) ? pc[soff[r]] : 0.f;
        }
    }
    __syncthreads();

    const int DDt[2][2] = {{0, -1}, {1, 0}};
    const int KKt[2][2] = {{1, 3}, {0, 2}};
    const int rbase = 2 * tyi * RW + txi;

    for (int c = 0; c < Cin; c++) {
        if ((c & (CC - 1)) == 0 && c + CC < Cin) stage_w(c / CC + 1);

        // prefetch next channel into registers
        float pref[RMAX];
        const bool havenext = (c + 1 < Cin);
        if (havenext) {
            const float* pc = inb + (size_t)(c + 1) * S;
#pragma unroll
            for (int r = 0; r < RMAX; r++) {
                pref[r] = ((sw_vld >> r) & 1u) ? pc[soff[r]] : 0.f;
            }
        }

        const float* vb = vsm[c & 1];
        const ull* wcU =
            wsmU[(c / CC) & 1] + ((size_t)og * OC * CC + (c & (CC - 1))) * 32;

#pragma unroll
        for (int jz = 0; jz < 3; jz++) {
            ull vp[4][3];
#pragma unroll
            for (int ry = 0; ry < 4; ry++) {
                const float* rp = vb + (tzi + jz) * PS + rbase + ry * RW;
                float e0 = rp[0];
                float e1 = rp[1];
                float o0 = rp[OB];
                float o1 = rp[OB + 1];
                vp[ry][0] = pack2f(e0, o0);  // (x0, x1)
                vp[ry][1] = pack2f(o0, e1);  // (x1, x2)
                vp[ry][2] = pack2f(e1, o1);  // (x2, x3)
            }
#pragma unroll
            for (int pz = 0; pz < 2; pz++)
#pragma unroll
                for (int sz = 0; sz < 2; sz++) {
                    if (1 + DDt[pz][sz] != jz) continue;  // compile-time pruned
                    const int kz = KKt[pz][sz];
#pragma unroll
                    for (int py = 0; py < 2; py++)
#pragma unroll
                        for (int sy = 0; sy < 2; sy++) {
                            const int jy0 = 1 + DDt[py][sy];
                            const int ky = KKt[py][sy];
#pragma unroll
                            for (int oc = 0; oc < OC; oc++) {
                                const ull wa =
                                    wcU[(oc * CC) * 32 + (kz * 4 + ky) * 2 + 0];
                                const ull wb =
                                    wcU[(oc * CC) * 32 + (kz * 4 + ky) * 2 + 1];
#pragma unroll
                                for (int cy = 0; cy < 2; cy++) {
                                    const int row = jy0 + cy;
#pragma unroll
                                    for (int cx = 0; cx < 2; cx++) {
                                        fma2(acc[oc][cy][cx][pz * 2 + py],
                                             vp[row][cx + 1], wa);
                                        fma2(acc[oc][cy][cx][pz * 2 + py],
                                             vp[row][cx], wb);
                                    }
                                }
                            }
                        }
                }
        }

        if (havenext) {
            float* vb1 = vsm[(c + 1) & 1];
#pragma unroll
            for (int r = 0; r < RMAX; r++) {
                if ((sw_act >> r) & 1u) vb1[tid + r * NT] = pref[r];
            }
        }
        __syncthreads();
    }

    // ---------------- epilogue (scalar stores; exact tiling) ----------------
    const int mz = bz + tzi;
    if (mz >= Dz) return;
    const int Ho = 2 * Hy, Wo = 2 * Wx;
    const int my0 = by + 2 * tyi;
    const int mx0 = bx + 2 * txi;

#pragma unroll
    for (int oc = 0; oc < OC; oc++) {
        const int o = obase + oc;
        const float bv = bias[o];
        float* ob = out + ((size_t)b * Cout + o) * (size_t)(2 * Dz) * Ho * Wo;
#pragma unroll
        for (int cy = 0; cy < 2; cy++) {
            int my = my0 + cy;
            if (my >= Hy) continue;
#pragma unroll
            for (int cx = 0; cx < 2; cx++) {
                int mx = mx0 + cx;
                if (mx >= Wx) continue;
#pragma unroll
                for (int pz = 0; pz < 2; pz++)
#pragma unroll
                    for (int py = 0; py < 2; py++) {
                        float2 a = unpk2(acc[oc][cy][cx][pz * 2 + py]);
                        float r0 = a.x + bv;
                        float r1 = a.y + bv;
                        if (SIG) {
                            r0 = 1.f / (1.f + __expf(-r0));
                            r1 = 1.f / (1.f + __expf(-r1));
                        }
                        size_t base = (size_t)(2 * mz + pz) * Ho * Wo +
                                      (size_t)(2 * my + py) * Wo + (size_t)(2 * mx);
                        ob[base] = r0;
                        ob[base + 1] = r1;
                    }
            }
        }
    }
}

// ---------------- host-side helpers ----------------
static void run_bn(float* t, int C, int S, const float* g, const float* be,
                   float* part, float* scale, float* shift) {
    dim3 gp(C, BN_NB);
    bn_partial<<<gp, 256>>>(t, C, S, part);
    bn_finalize<<<(C + 127) / 128, 128>>>(part, C, (float)(BATCH * S), g, be, scale, shift);
    size_t total = (size_t)BATCH * C * S;
    bn_apply_relu<<<(unsigned)((total + 255) / 256), 256>>>(t, C, S, scale, shift);
}

template <int TILEY, int TILEX, int RW, int OB, int PSPAD, int OG, int OC, int CC,
          bool SIG>
static void run_convt8(const float* in, const float* wt, const float* bias,
                       float* out, int Cin, int Cout, int Dz, int Hy, int Wx) {
    int ntx = Wx / TILEX;
    int nty = Hy / TILEY;
    int ntz = Dz / 4;
    dim3 grid(ntx * nty * ntz, Cout / (OG * OC), BATCH);
    convt8_kernel<TILEY, TILEX, RW, OB, PSPAD, OG, OC, CC, SIG>
        <<<grid, TILEY * TILEX * OG>>>(in, wt, bias, out, Cin, Cout, Dz, Hy, Wx,
                                       ntx, nty);
}

extern "C" void kernel_launch(void* const* d_in, const int* in_sizes, int n_in,
                              void* d_out, int out_size) {
    const float* x_in = (const float*)d_in[0];
    const float* y_in = (const float*)d_in[1];
    const float* tables = (const float*)d_in[2];
    const float* g0 = (const float*)d_in[3];
    const float* be0 = (const float*)d_in[4];
    const float* g1 = (const float*)d_in[5];
    const float* be1 = (const float*)d_in[6];
    const float* g2 = (const float*)d_in[7];
    const float* be2 = (const float*)d_in[8];
    const float* g3 = (const float*)d_in[9];
    const float* be3 = (const float*)d_in[10];
    const float* g4 = (const float*)d_in[11];
    const float* be4 = (const float*)d_in[12];
    const float* w1 = (const float*)d_in[13];
    const float* b1 = (const float*)d_in[14];
    const float* w2 = (const float*)d_in[15];
    const float* b2 = (const float*)d_in[16];
    const float* w3 = (const float*)d_in[17];
    const float* b3 = (const float*)d_in[18];
    const float* w4 = (const float*)d_in[19];
    const float* b4 = (const float*)d_in[20];
    const float* w5 = (const float*)d_in[21];
    const float* b5 = (const float*)d_in[22];

    float *wproj, *t0, *t1, *t2, *t3, *t4, *part, *scale, *shift;
    cudaGetSymbolAddress((void**)&wproj, g_wproj);
    cudaGetSymbolAddress((void**)&t0, g_t0);
    cudaGetSymbolAddress((void**)&t1, g_t1);
    cudaGetSymbolAddress((void**)&t2, g_t2);
    cudaGetSymbolAddress((void**)&t3, g_t3);
    cudaGetSymbolAddress((void**)&t4, g_t4);
    cudaGetSymbolAddress((void**)&part, g_part);
    cudaGetSymbolAddress((void**)&scale, g_scale);
    cudaGetSymbolAddress((void**)&shift, g_shift);

    // 1) hypernet weights
    {
        int tot = NHEADS * CPROJ * CIN0;
        hyper_kernel<<<(tot + 255) / 256, 256>>>(y_in, tables, wproj);
    }
    // 2) dynamic 1x1x1 projection -> t0 [2,1024,4,6,8]
    {
        dim3 pg(128, BATCH);
        proj_kernel2<<<pg, 192>>>(x_in, wproj, t0);
    }
    // 3) decoder stack (OC=2 output channels per thread except L5)
    // L1: TILE 6x8,  RW=18,OB=8,PSPAD=28, OG=2,OC=2,CC=16 -> 96 thr, smem ~40KB
    // L2: TILE 4x16, RW=24,OB=12,PSPAD=24, OG=2,OC=2,CC=16 -> 128 thr, ~40KB
    // L3/L4: TILE 8x16, RW=20,OB=10, OG=1,OC=2,CC=16 -> 256 thr, ~26KB
    // L5: Cout=1 -> OC=1, CC=32
    run_bn(t0, 1024, 4 * 6 * 8, g0, be0, part, scale, shift);
    run_convt8<6, 8, 18, 8, 28, 2, 2, 16, false>(t0, w1, b1, t1, 1024, 512,
                                                 4, 6, 8);
    run_bn(t1, 512, 8 * 12 * 16, g1, be1, part, scale, shift);
    run_convt8<4, 16, 24, 12, 24, 2, 2, 16, false>(t1, w2, b2, t2, 512, 256,
                                                   8, 12, 16);
    run_bn(t2, 256, 16 * 24 * 32, g2, be2, part, scale, shift);
    run_convt8<8, 16, 20, 10, 0, 1, 2, 16, false>(t2, w3, b3, t3, 256, 128,
                                                  16, 24, 32);
    run_bn(t3, 128, 32 * 48 * 64, g3, be3, part, scale, shift);
    run_convt8<8, 16, 20, 10, 0, 1, 2, 16, false>(t3, w4, b4, t4, 128, 32,
                                                  32, 48, 64);
    run_bn(t4, 32, 64 * 96 * 128, g4, be4, part, scale, shift);
    run_convt8<8, 16, 20, 10, 0, 1, 1, 32, true>(t4, w5, b5, (float*)d_out,
                                                 32, 1, 64, 96, 128);
}